// round 3
// baseline (speedup 1.0000x reference)
#include <cuda_runtime.h>
#include <cstdint>

// ---------------------------------------------------------------------------
// LIIF3D fused kernel (fp32, packed f32x2 FMA).
// Pipeline per CTA: 8 queries x 8 shifts = 64 rows.
//   Stage A: trilinear sampling from channel-last feat copy (L2-resident)
//   Stage B: 3 fused GEMMs (71->256->256->256) in shared memory, f32x2 FMA,
//            cp.async double-buffered weight streaming
//   Stage C: final 256->1 dot + area-weighted combine of the 8 shifts
// ---------------------------------------------------------------------------

#define NQ    131072
#define SMEM_BYTES 190976   // 47744 floats

// channel-last feature volume: (z,y,x,c), 32*32*32*64 floats = 8 MB
__device__ float g_feat_t[32 * 32 * 32 * 64];

// ---------------- small PTX helpers ----------------
__device__ __forceinline__ unsigned smem_addr_u32(const void* p) {
    unsigned r;
    asm("{ .reg .u64 t; cvta.to.shared.u64 t, %1; cvt.u32.u64 %0, t; }"
        : "=r"(r) : "l"(p));
    return r;
}
__device__ __forceinline__ void cp_async16(unsigned s, const void* g) {
    asm volatile("cp.async.cg.shared.global [%0], [%1], 16;" :: "r"(s), "l"(g));
}
__device__ __forceinline__ void cp_commit() { asm volatile("cp.async.commit_group;"); }
__device__ __forceinline__ void cp_wait1()  { asm volatile("cp.async.wait_group 1;"); }
__device__ __forceinline__ void cp_wait0()  { asm volatile("cp.async.wait_group 0;"); }

__device__ __forceinline__ unsigned long long pack2(float x, float y) {
    unsigned long long r;
    asm("mov.b64 %0, {%1, %2};" : "=l"(r) : "f"(x), "f"(y));
    return r;
}
__device__ __forceinline__ float2 unpk2(unsigned long long v) {
    float2 r;
    asm("mov.b64 {%0, %1}, %2;" : "=f"(r.x), "=f"(r.y) : "l"(v));
    return r;
}
// packed dual fp32 FMA (Blackwell f32x2 pipe, 2 FMAs per instruction)
__device__ __forceinline__ unsigned long long ffma2(unsigned long long a,
                                                    unsigned long long b,
                                                    unsigned long long c) {
    unsigned long long d;
    asm("fma.rn.f32x2 %0, %1, %2, %3;" : "=l"(d) : "l"(a), "l"(b), "l"(c));
    return d;
}

// ---------------- feat transpose: (C,D,H,W) -> (spatial, C) ----------------
__global__ void transpose_feat(const float* __restrict__ feat) {
    __shared__ float tile[64][65];
    const int sp0 = blockIdx.x * 64;          // 64 spatial positions per block
    const int tx = threadIdx.x;               // 0..63
    const int ty = threadIdx.y;               // 0..3
    #pragma unroll
    for (int c = ty; c < 64; c += 4)
        tile[c][tx] = feat[c * 32768 + sp0 + tx];
    __syncthreads();
    #pragma unroll
    for (int s = ty; s < 64; s += 4)
        g_feat_t[(size_t)(sp0 + s) * 64 + tx] = tile[tx][s];
}

// ---------------- fused shared-memory GEMM ----------------
// Computes Cs[N=256][64] (k-major, ld=68) = relu( As[64][K] @ Wg[K][256] + bias )
// AKM = true  : As is k-major [K][lda]  (ld = 68, vectorized LDS.128 broadcast)
// AKM = false : As is row-major [64][lda] (ld = 72, scalar reads; only K=71 layer)
template <bool AKM>
__device__ __forceinline__ void gemm_tile(
    const float* As, int lda, int K,
    const float* __restrict__ Wg, const float* __restrict__ bias,
    float* Cs, float* wbuf /* [2][16][256] */, int t)
{
    const int tn = t & 15;       // 16 col-groups of 16 columns
    const int tm = t >> 4;       // 16 row-groups of 4 rows
    const int n0 = tn * 16;

    unsigned long long acc[4][8];
    #pragma unroll
    for (int j = 0; j < 8; j++) {
        unsigned long long bp = pack2(bias[n0 + 2 * j], bias[n0 + 2 * j + 1]);
        #pragma unroll
        for (int m = 0; m < 4; m++) acc[m][j] = bp;
    }

    const int ntile = (K + 15) >> 4;
    const unsigned wb0 = smem_addr_u32(wbuf);

    // preload k-tile 0
    {
        int kend = K < 16 ? K : 16;
        int nf4 = kend * 64;
        const float4* src = (const float4*)Wg;
        #pragma unroll
        for (int i = 0; i < 4; i++) {
            int f = t + i * 256;
            if (f < nf4) cp_async16(wb0 + f * 16, src + f);
        }
        cp_commit();
    }

    for (int kb = 0; kb < ntile; kb++) {
        if (kb + 1 < ntile) {
            int kend = K - (kb + 1) * 16; if (kend > 16) kend = 16;
            int nf4 = kend * 64;
            const float4* src = (const float4*)(Wg + (kb + 1) * 16 * 256);
            unsigned dst = wb0 + (((kb + 1) & 1) ? 16384u : 0u);
            #pragma unroll
            for (int i = 0; i < 4; i++) {
                int f = t + i * 256;
                if (f < nf4) cp_async16(dst + f * 16, src + f);
            }
            cp_commit();
            cp_wait1();
        } else {
            cp_wait0();
        }
        __syncthreads();

        const float* wb = wbuf + (kb & 1) * 4096;
        int kend = K - kb * 16; if (kend > 16) kend = 16;

        #pragma unroll 4
        for (int kk = 0; kk < kend; kk++) {
            const int k = kb * 16 + kk;
            unsigned long long ap[4];
            if (AKM) {
                float4 av = *(const float4*)(As + k * lda + tm * 4);
                ap[0] = pack2(av.x, av.x); ap[1] = pack2(av.y, av.y);
                ap[2] = pack2(av.z, av.z); ap[3] = pack2(av.w, av.w);
            } else {
                float a0 = As[(tm * 4 + 0) * lda + k];
                float a1 = As[(tm * 4 + 1) * lda + k];
                float a2 = As[(tm * 4 + 2) * lda + k];
                float a3 = As[(tm * 4 + 3) * lda + k];
                ap[0] = pack2(a0, a0); ap[1] = pack2(a1, a1);
                ap[2] = pack2(a2, a2); ap[3] = pack2(a3, a3);
            }
            const unsigned long long* wrow =
                (const unsigned long long*)(wb + kk * 256 + n0);
            unsigned long long wv[8];
            #pragma unroll
            for (int j = 0; j < 8; j++) wv[j] = wrow[j];
            #pragma unroll
            for (int m = 0; m < 4; m++)
                #pragma unroll
                for (int j = 0; j < 8; j++)
                    acc[m][j] = ffma2(ap[m], wv[j], acc[m][j]);
        }
        __syncthreads();
    }

    // epilogue: relu, store k-major [col][row], ld = 68 (conflict-free)
    #pragma unroll
    for (int j = 0; j < 8; j++) {
        float2 v0 = unpk2(acc[0][j]), v1 = unpk2(acc[1][j]);
        float2 v2 = unpk2(acc[2][j]), v3 = unpk2(acc[3][j]);
        float4 cx = make_float4(fmaxf(v0.x, 0.f), fmaxf(v1.x, 0.f),
                                fmaxf(v2.x, 0.f), fmaxf(v3.x, 0.f));
        float4 cy = make_float4(fmaxf(v0.y, 0.f), fmaxf(v1.y, 0.f),
                                fmaxf(v2.y, 0.f), fmaxf(v3.y, 0.f));
        *(float4*)(Cs + (n0 + 2 * j)     * 68 + tm * 4) = cx;
        *(float4*)(Cs + (n0 + 2 * j + 1) * 68 + tm * 4) = cy;
    }
}

// ---------------- main fused kernel ----------------
__global__ void __launch_bounds__(256, 1) liif_kernel(
    const float* __restrict__ coord, const float* __restrict__ cell,
    const float* __restrict__ W0, const float* __restrict__ b0,
    const float* __restrict__ W1, const float* __restrict__ b1,
    const float* __restrict__ W2, const float* __restrict__ b2,
    const float* __restrict__ W3, const float* __restrict__ b3,
    float* __restrict__ out)
{
    extern __shared__ float smem[];
    float* Xsr   = smem;                  // [64][72] row-major features
    float* H0    = smem + 4608;           // [256][68] k-major
    float* H1    = H0 + 17408;            // [256][68]
    float* wbuf  = H1 + 17408;            // [2][16][256]
    float* pred  = wbuf + 8192;           // [64]
    float* areaS = pred + 64;             // [64]

    const int t = threadIdx.x;
    const int warp = t >> 5, lane = t & 31;
    const int q0 = blockIdx.x * 8;

    // ---- Stage A: sampling + feature vector build (each warp: 8 rows) ----
    for (int rr = warp; rr < 64; rr += 8) {
        const int q = q0 + (rr >> 3);
        const int s = rr & 7;
        const float c0 = coord[q * 3 + 0], c1 = coord[q * 3 + 1], c2 = coord[q * 3 + 2];
        const float l0 = cell[q * 3 + 0],  l1 = cell[q * 3 + 1],  l2 = cell[q * 3 + 2];
        const float r = 1.0f / 32.0f;
        float g0 = c0 + ((s & 4) ? r : -r) + 1e-6f;
        float g1 = c1 + ((s & 2) ? r : -r) + 1e-6f;
        float g2 = c2 + ((s & 1) ? r : -r) + 1e-6f;
        const float lo = -1.0f + 1e-6f, hi = 1.0f - 1e-6f;
        g0 = fminf(fmaxf(g0, lo), hi);
        g1 = fminf(fmaxf(g1, lo), hi);
        g2 = fminf(fmaxf(g2, lo), hi);
        // c[...,0] indexes D (z), c[...,1] indexes H (y), c[...,2] indexes W (x)
        const float z = (g0 + 1.0f) * 16.0f - 0.5f;
        const float y = (g1 + 1.0f) * 16.0f - 0.5f;
        const float x = (g2 + 1.0f) * 16.0f - 0.5f;
        const float zf = floorf(z), yf = floorf(y), xf = floorf(x);
        const float wz = z - zf, wy = y - yf, wx = x - xf;
        const int iz0 = min(max((int)zf, 0), 31), iz1 = min(max((int)zf + 1, 0), 31);
        const int iy0 = min(max((int)yf, 0), 31), iy1 = min(max((int)yf + 1, 0), 31);
        const int ix0 = min(max((int)xf, 0), 31), ix1 = min(max((int)xf + 1, 0), 31);
        // q_coord: channel 0 = lx interp (x indices), 1 = ly (y), 2 = lz (z)
        const float st = 2.0f / 31.0f;
        const float qc0 = (1.0f - wx) * (-1.0f + ix0 * st) + wx * (-1.0f + ix1 * st);
        const float qc1 = (1.0f - wy) * (-1.0f + iy0 * st) + wy * (-1.0f + iy1 * st);
        const float qc2 = (1.0f - wz) * (-1.0f + iz0 * st) + wz * (-1.0f + iz1 * st);
        const float rc0 = (c0 - qc0) * 32.0f;
        const float rc1 = (c1 - qc1) * 32.0f;
        const float rc2 = (c2 - qc2) * 32.0f;

        const float w00 = (1.0f - wz) * (1.0f - wy), w01 = (1.0f - wz) * wy;
        const float w10 = wz * (1.0f - wy),          w11 = wz * wy;
        const float mwx = 1.0f - wx;
        const int b00 = (iz0 * 32 + iy0) * 32, b01 = (iz0 * 32 + iy1) * 32;
        const int b10 = (iz1 * 32 + iy0) * 32, b11 = (iz1 * 32 + iy1) * 32;
        const float* F = g_feat_t + lane * 2;   // lane owns channels 2l, 2l+1
        float2 acc = make_float2(0.f, 0.f);
        float2 v;
        v = *(const float2*)(F + (size_t)(b00 + ix0) * 64); acc.x += w00 * mwx * v.x; acc.y += w00 * mwx * v.y;
        v = *(const float2*)(F + (size_t)(b00 + ix1) * 64); acc.x += w00 * wx  * v.x; acc.y += w00 * wx  * v.y;
        v = *(const float2*)(F + (size_t)(b01 + ix0) * 64); acc.x += w01 * mwx * v.x; acc.y += w01 * mwx * v.y;
        v = *(const float2*)(F + (size_t)(b01 + ix1) * 64); acc.x += w01 * wx  * v.x; acc.y += w01 * wx  * v.y;
        v = *(const float2*)(F + (size_t)(b10 + ix0) * 64); acc.x += w10 * mwx * v.x; acc.y += w10 * mwx * v.y;
        v = *(const float2*)(F + (size_t)(b10 + ix1) * 64); acc.x += w10 * wx  * v.x; acc.y += w10 * wx  * v.y;
        v = *(const float2*)(F + (size_t)(b11 + ix0) * 64); acc.x += w11 * mwx * v.x; acc.y += w11 * mwx * v.y;
        v = *(const float2*)(F + (size_t)(b11 + ix1) * 64); acc.x += w11 * wx  * v.x; acc.y += w11 * wx  * v.y;

        *(float2*)(Xsr + rr * 72 + lane * 2) = acc;
        if (lane == 0) {
            Xsr[rr * 72 + 64] = rc0; Xsr[rr * 72 + 65] = rc1; Xsr[rr * 72 + 66] = rc2;
            Xsr[rr * 72 + 67] = l0 * 32.0f;
            Xsr[rr * 72 + 68] = l1 * 32.0f;
            Xsr[rr * 72 + 69] = l2 * 32.0f;
            float cv = fabsf(l0 * l1 * l2);
            Xsr[rr * 72 + 70] = fminf(fmaxf(8.0f / (cv + 1e-8f), 1.0f), 64.0f);
            areaS[rr] = fabsf(rc0 * rc1 * rc2) + 1e-9f;
        }
    }
    // (first __syncthreads inside gemm_tile orders Xsr writes before reads)

    // ---- Stage B: MLP ----
    gemm_tile<false>(Xsr, 72, 71,  W0, b0, H0, wbuf, t);
    gemm_tile<true >(H0,  68, 256, W1, b1, H1, wbuf, t);
    gemm_tile<true >(H1,  68, 256, W2, b2, H0, wbuf, t);
    __syncthreads();

    // ---- Stage C: final 256->1 dot (per row), then area-weighted combine ----
    for (int rr = warp; rr < 64; rr += 8) {
        float p = 0.f;
        #pragma unroll
        for (int kk = 0; kk < 8; kk++) {
            const int k = kk * 32 + lane;
            p += H0[k * 68 + rr] * W3[k];
        }
        #pragma unroll
        for (int o = 16; o; o >>= 1) p += __shfl_xor_sync(0xffffffffu, p, o);
        if (lane == 0) pred[rr] = p + b3[0];
    }
    __syncthreads();

    if (t < 8) {
        const int r0 = t * 8;
        float tot = 0.f, o = 0.f;
        #pragma unroll
        for (int s = 0; s < 8; s++) tot += areaS[r0 + s];
        #pragma unroll
        for (int s = 0; s < 8; s++) o += pred[r0 + s] * areaS[r0 + (7 - s)];
        out[q0 + t] = o / tot;
    }
}

// ---------------- launch ----------------
extern "C" void kernel_launch(void* const* d_in, const int* in_sizes, int n_in,
                              void* d_out, int out_size) {
    (void)in_sizes; (void)n_in; (void)out_size;
    const float* inp   = (const float*)d_in[0];
    const float* coord = (const float*)d_in[1];
    const float* cell  = (const float*)d_in[2];
    const float* W0 = (const float*)d_in[3];
    const float* b0 = (const float*)d_in[4];
    const float* W1 = (const float*)d_in[5];
    const float* b1 = (const float*)d_in[6];
    const float* W2 = (const float*)d_in[7];
    const float* b2 = (const float*)d_in[8];
    const float* W3 = (const float*)d_in[9];
    const float* b3 = (const float*)d_in[10];
    float* out = (float*)d_out;

    cudaFuncSetAttribute(liif_kernel,
                         cudaFuncAttributeMaxDynamicSharedMemorySize, SMEM_BYTES);

    transpose_feat<<<512, dim3(64, 4)>>>(inp);
    liif_kernel<<<NQ / 8, 256, SMEM_BYTES>>>(coord, cell,
                                             W0, b0, W1, b1, W2, b2, W3, b3,
                                             out);
}

// round 4
// speedup vs baseline: 2.4906x; 2.4906x over previous
#include <cuda_runtime.h>
#include <cstdint>

// ---------------------------------------------------------------------------
// LIIF3D fused kernel (fp32, packed f32x2 FMA).
// R3 change: interleaved column ownership (c = j*32 + 2*tn) kills the 8-way
// bank conflict on weight-tile LDS.64 reads (was 520 smem cyc/kk vs 128 FMA
// cyc/kk -> smem-bound). Now 72 smem cyc/kk -> FMA-issue-bound.
// ---------------------------------------------------------------------------

#define NQ    131072
#define SMEM_BYTES 191488   // 47872 floats

// channel-last feature volume: (z,y,x,c), 32*32*32*64 floats = 8 MB
__device__ float g_feat_t[32 * 32 * 32 * 64];

// ---------------- small PTX helpers ----------------
__device__ __forceinline__ unsigned smem_addr_u32(const void* p) {
    unsigned r;
    asm("{ .reg .u64 t; cvta.to.shared.u64 t, %1; cvt.u32.u64 %0, t; }"
        : "=r"(r) : "l"(p));
    return r;
}
__device__ __forceinline__ void cp_async16(unsigned s, const void* g) {
    asm volatile("cp.async.cg.shared.global [%0], [%1], 16;" :: "r"(s), "l"(g));
}
__device__ __forceinline__ void cp_commit() { asm volatile("cp.async.commit_group;"); }
__device__ __forceinline__ void cp_wait1()  { asm volatile("cp.async.wait_group 1;"); }
__device__ __forceinline__ void cp_wait0()  { asm volatile("cp.async.wait_group 0;"); }

__device__ __forceinline__ unsigned long long pack2(float x, float y) {
    unsigned long long r;
    asm("mov.b64 %0, {%1, %2};" : "=l"(r) : "f"(x), "f"(y));
    return r;
}
__device__ __forceinline__ float2 unpk2(unsigned long long v) {
    float2 r;
    asm("mov.b64 {%0, %1}, %2;" : "=f"(r.x), "=f"(r.y) : "l"(v));
    return r;
}
// packed dual fp32 FMA (Blackwell f32x2 pipe, 2 FMAs per instruction)
__device__ __forceinline__ unsigned long long ffma2(unsigned long long a,
                                                    unsigned long long b,
                                                    unsigned long long c) {
    unsigned long long d;
    asm("fma.rn.f32x2 %0, %1, %2, %3;" : "=l"(d) : "l"(a), "l"(b), "l"(c));
    return d;
}

// ---------------- feat transpose: (C,D,H,W) -> (spatial, C) ----------------
__global__ void transpose_feat(const float* __restrict__ feat) {
    __shared__ float tile[64][65];
    const int sp0 = blockIdx.x * 64;          // 64 spatial positions per block
    const int tx = threadIdx.x;               // 0..63
    const int ty = threadIdx.y;               // 0..3
    #pragma unroll
    for (int c = ty; c < 64; c += 4)
        tile[c][tx] = feat[c * 32768 + sp0 + tx];
    __syncthreads();
    #pragma unroll
    for (int s = ty; s < 64; s += 4)
        g_feat_t[(size_t)(sp0 + s) * 64 + tx] = tile[tx][s];
}

// ---------------- fused shared-memory GEMM ----------------
// Computes Cs[N=256][64] (k-major, ld=68) = relu( As[64][K] @ Wg[K][256] + bias )
// Thread t (tn = t&15, tm = t>>4) owns rows [4tm,4tm+4) and column pairs
//   c_j = j*32 + 2*tn, j = 0..7   (interleaved -> conflict-free LDS of wbuf)
// AKM = true  : As is k-major [K][lda]  (ld = 68, LDS.128 broadcast)
// AKM = false : As is row-major [64][lda] (ld = 74; only K=71 layer)
template <bool AKM>
__device__ __forceinline__ void gemm_tile(
    const float* As, int lda, int K,
    const float* __restrict__ Wg, const float* __restrict__ bias,
    float* Cs, float* wbuf /* [2][16][256] */, int t)
{
    const int tn = t & 15;       // owns interleaved column pairs j*32 + 2*tn
    const int tm = t >> 4;       // 16 row-groups of 4 rows
    const int cb = 2 * tn;       // column base within each 32-col group

    unsigned long long acc[4][8];
    #pragma unroll
    for (int j = 0; j < 8; j++) {
        unsigned long long bp = pack2(bias[j * 32 + cb], bias[j * 32 + cb + 1]);
        #pragma unroll
        for (int m = 0; m < 4; m++) acc[m][j] = bp;
    }

    const int ntile = (K + 15) >> 4;
    const unsigned wb0 = smem_addr_u32(wbuf);

    // preload k-tile 0
    {
        int kend = K < 16 ? K : 16;
        int nf4 = kend * 64;
        const float4* src = (const float4*)Wg;
        #pragma unroll
        for (int i = 0; i < 4; i++) {
            int f = t + i * 256;
            if (f < nf4) cp_async16(wb0 + f * 16, src + f);
        }
        cp_commit();
    }

    for (int kb = 0; kb < ntile; kb++) {
        if (kb + 1 < ntile) {
            int kend = K - (kb + 1) * 16; if (kend > 16) kend = 16;
            int nf4 = kend * 64;
            const float4* src = (const float4*)(Wg + (kb + 1) * 16 * 256);
            unsigned dst = wb0 + (((kb + 1) & 1) ? 16384u : 0u);
            #pragma unroll
            for (int i = 0; i < 4; i++) {
                int f = t + i * 256;
                if (f < nf4) cp_async16(dst + f * 16, src + f);
            }
            cp_commit();
            cp_wait1();
        } else {
            cp_wait0();
        }
        __syncthreads();

        const float* wb = wbuf + (kb & 1) * 4096;
        int kend = K - kb * 16; if (kend > 16) kend = 16;

        #pragma unroll 4
        for (int kk = 0; kk < kend; kk++) {
            const int k = kb * 16 + kk;
            unsigned long long ap[4];
            if (AKM) {
                float4 av = *(const float4*)(As + k * lda + tm * 4);
                ap[0] = pack2(av.x, av.x); ap[1] = pack2(av.y, av.y);
                ap[2] = pack2(av.z, av.z); ap[3] = pack2(av.w, av.w);
            } else {
                float a0 = As[(tm * 4 + 0) * lda + k];
                float a1 = As[(tm * 4 + 1) * lda + k];
                float a2 = As[(tm * 4 + 2) * lda + k];
                float a3 = As[(tm * 4 + 3) * lda + k];
                ap[0] = pack2(a0, a0); ap[1] = pack2(a1, a1);
                ap[2] = pack2(a2, a2); ap[3] = pack2(a3, a3);
            }
            // conflict-free: 16 distinct consecutive 8B words per j,
            // 128B-aligned base (kk*256 + j*32 floats); upper half broadcasts
            const float* wrow = wb + kk * 256 + cb;
            unsigned long long wv[8];
            #pragma unroll
            for (int j = 0; j < 8; j++)
                wv[j] = *(const unsigned long long*)(wrow + j * 32);
            #pragma unroll
            for (int m = 0; m < 4; m++)
                #pragma unroll
                for (int j = 0; j < 8; j++)
                    acc[m][j] = ffma2(ap[m], wv[j], acc[m][j]);
        }
        __syncthreads();
    }

    // epilogue: relu, store k-major [col][row], ld = 68.
    // Warp covers 8 distinct float4 bank-positions x 4 lanes = 4 wavefronts
    // per STS.128 = the 512B/128B floor (no conflict penalty).
    #pragma unroll
    for (int j = 0; j < 8; j++) {
        const int c = j * 32 + cb;
        float2 v0 = unpk2(acc[0][j]), v1 = unpk2(acc[1][j]);
        float2 v2 = unpk2(acc[2][j]), v3 = unpk2(acc[3][j]);
        float4 cx = make_float4(fmaxf(v0.x, 0.f), fmaxf(v1.x, 0.f),
                                fmaxf(v2.x, 0.f), fmaxf(v3.x, 0.f));
        float4 cy = make_float4(fmaxf(v0.y, 0.f), fmaxf(v1.y, 0.f),
                                fmaxf(v2.y, 0.f), fmaxf(v3.y, 0.f));
        *(float4*)(Cs + (c)     * 68 + tm * 4) = cx;
        *(float4*)(Cs + (c + 1) * 68 + tm * 4) = cy;
    }
}

// ---------------- main fused kernel ----------------
__global__ void __launch_bounds__(256, 1) liif_kernel(
    const float* __restrict__ coord, const float* __restrict__ cell,
    const float* __restrict__ W0, const float* __restrict__ b0,
    const float* __restrict__ W1, const float* __restrict__ b1,
    const float* __restrict__ W2, const float* __restrict__ b2,
    const float* __restrict__ W3, const float* __restrict__ b3,
    float* __restrict__ out)
{
    extern __shared__ float smem[];
    float* Xsr   = smem;                  // [64][74] row-major features
    float* H0    = smem + 4736;           // [256][68] k-major
    float* H1    = H0 + 17408;            // [256][68]
    float* wbuf  = H1 + 17408;            // [2][16][256]
    float* pred  = wbuf + 8192;           // [64]
    float* areaS = pred + 64;             // [64]

    const int t = threadIdx.x;
    const int warp = t >> 5, lane = t & 31;
    const int q0 = blockIdx.x * 8;

    // ---- Stage A: sampling + feature vector build (each warp: 8 rows) ----
    for (int rr = warp; rr < 64; rr += 8) {
        const int q = q0 + (rr >> 3);
        const int s = rr & 7;
        const float c0 = coord[q * 3 + 0], c1 = coord[q * 3 + 1], c2 = coord[q * 3 + 2];
        const float l0 = cell[q * 3 + 0],  l1 = cell[q * 3 + 1],  l2 = cell[q * 3 + 2];
        const float r = 1.0f / 32.0f;
        float g0 = c0 + ((s & 4) ? r : -r) + 1e-6f;
        float g1 = c1 + ((s & 2) ? r : -r) + 1e-6f;
        float g2 = c2 + ((s & 1) ? r : -r) + 1e-6f;
        const float lo = -1.0f + 1e-6f, hi = 1.0f - 1e-6f;
        g0 = fminf(fmaxf(g0, lo), hi);
        g1 = fminf(fmaxf(g1, lo), hi);
        g2 = fminf(fmaxf(g2, lo), hi);
        // c[...,0] indexes D (z), c[...,1] indexes H (y), c[...,2] indexes W (x)
        const float z = (g0 + 1.0f) * 16.0f - 0.5f;
        const float y = (g1 + 1.0f) * 16.0f - 0.5f;
        const float x = (g2 + 1.0f) * 16.0f - 0.5f;
        const float zf = floorf(z), yf = floorf(y), xf = floorf(x);
        const float wz = z - zf, wy = y - yf, wx = x - xf;
        const int iz0 = min(max((int)zf, 0), 31), iz1 = min(max((int)zf + 1, 0), 31);
        const int iy0 = min(max((int)yf, 0), 31), iy1 = min(max((int)yf + 1, 0), 31);
        const int ix0 = min(max((int)xf, 0), 31), ix1 = min(max((int)xf + 1, 0), 31);
        // q_coord: channel 0 = lx interp (x indices), 1 = ly (y), 2 = lz (z)
        const float st = 2.0f / 31.0f;
        const float qc0 = (1.0f - wx) * (-1.0f + ix0 * st) + wx * (-1.0f + ix1 * st);
        const float qc1 = (1.0f - wy) * (-1.0f + iy0 * st) + wy * (-1.0f + iy1 * st);
        const float qc2 = (1.0f - wz) * (-1.0f + iz0 * st) + wz * (-1.0f + iz1 * st);
        const float rc0 = (c0 - qc0) * 32.0f;
        const float rc1 = (c1 - qc1) * 32.0f;
        const float rc2 = (c2 - qc2) * 32.0f;

        const float w00 = (1.0f - wz) * (1.0f - wy), w01 = (1.0f - wz) * wy;
        const float w10 = wz * (1.0f - wy),          w11 = wz * wy;
        const float mwx = 1.0f - wx;
        const int b00 = (iz0 * 32 + iy0) * 32, b01 = (iz0 * 32 + iy1) * 32;
        const int b10 = (iz1 * 32 + iy0) * 32, b11 = (iz1 * 32 + iy1) * 32;
        const float* F = g_feat_t + lane * 2;   // lane owns channels 2l, 2l+1
        float2 acc = make_float2(0.f, 0.f);
        float2 v;
        v = *(const float2*)(F + (size_t)(b00 + ix0) * 64); acc.x += w00 * mwx * v.x; acc.y += w00 * mwx * v.y;
        v = *(const float2*)(F + (size_t)(b00 + ix1) * 64); acc.x += w00 * wx  * v.x; acc.y += w00 * wx  * v.y;
        v = *(const float2*)(F + (size_t)(b01 + ix0) * 64); acc.x += w01 * mwx * v.x; acc.y += w01 * mwx * v.y;
        v = *(const float2*)(F + (size_t)(b01 + ix1) * 64); acc.x += w01 * wx  * v.x; acc.y += w01 * wx  * v.y;
        v = *(const float2*)(F + (size_t)(b10 + ix0) * 64); acc.x += w10 * mwx * v.x; acc.y += w10 * mwx * v.y;
        v = *(const float2*)(F + (size_t)(b10 + ix1) * 64); acc.x += w10 * wx  * v.x; acc.y += w10 * wx  * v.y;
        v = *(const float2*)(F + (size_t)(b11 + ix0) * 64); acc.x += w11 * mwx * v.x; acc.y += w11 * mwx * v.y;
        v = *(const float2*)(F + (size_t)(b11 + ix1) * 64); acc.x += w11 * wx  * v.x; acc.y += w11 * wx  * v.y;

        *(float2*)(Xsr + rr * 74 + lane * 2) = acc;
        if (lane == 0) {
            Xsr[rr * 74 + 64] = rc0; Xsr[rr * 74 + 65] = rc1; Xsr[rr * 74 + 66] = rc2;
            Xsr[rr * 74 + 67] = l0 * 32.0f;
            Xsr[rr * 74 + 68] = l1 * 32.0f;
            Xsr[rr * 74 + 69] = l2 * 32.0f;
            float cv = fabsf(l0 * l1 * l2);
            Xsr[rr * 74 + 70] = fminf(fmaxf(8.0f / (cv + 1e-8f), 1.0f), 64.0f);
            areaS[rr] = fabsf(rc0 * rc1 * rc2) + 1e-9f;
        }
    }
    // (first __syncthreads inside gemm_tile orders Xsr writes before reads)

    // ---- Stage B: MLP ----
    gemm_tile<false>(Xsr, 74, 71,  W0, b0, H0, wbuf, t);
    gemm_tile<true >(H0,  68, 256, W1, b1, H1, wbuf, t);
    gemm_tile<true >(H1,  68, 256, W2, b2, H0, wbuf, t);
    __syncthreads();

    // ---- Stage C: final 256->1 dot (per row), then area-weighted combine ----
    for (int rr = warp; rr < 64; rr += 8) {
        float p = 0.f;
        #pragma unroll
        for (int kk = 0; kk < 8; kk++) {
            const int k = kk * 32 + lane;
            p += H0[k * 68 + rr] * W3[k];
        }
        #pragma unroll
        for (int o = 16; o; o >>= 1) p += __shfl_xor_sync(0xffffffffu, p, o);
        if (lane == 0) pred[rr] = p + b3[0];
    }
    __syncthreads();

    if (t < 8) {
        const int r0 = t * 8;
        float tot = 0.f, o = 0.f;
        #pragma unroll
        for (int s = 0; s < 8; s++) tot += areaS[r0 + s];
        #pragma unroll
        for (int s = 0; s < 8; s++) o += pred[r0 + s] * areaS[r0 + (7 - s)];
        out[q0 + t] = o / tot;
    }
}

// ---------------- launch ----------------
extern "C" void kernel_launch(void* const* d_in, const int* in_sizes, int n_in,
                              void* d_out, int out_size) {
    (void)in_sizes; (void)n_in; (void)out_size;
    const float* inp   = (const float*)d_in[0];
    const float* coord = (const float*)d_in[1];
    const float* cell  = (const float*)d_in[2];
    const float* W0 = (const float*)d_in[3];
    const float* b0 = (const float*)d_in[4];
    const float* W1 = (const float*)d_in[5];
    const float* b1 = (const float*)d_in[6];
    const float* W2 = (const float*)d_in[7];
    const float* b2 = (const float*)d_in[8];
    const float* W3 = (const float*)d_in[9];
    const float* b3 = (const float*)d_in[10];
    float* out = (float*)d_out;

    cudaFuncSetAttribute(liif_kernel,
                         cudaFuncAttributeMaxDynamicSharedMemorySize, SMEM_BYTES);

    transpose_feat<<<512, dim3(64, 4)>>>(inp);
    liif_kernel<<<NQ / 8, 256, SMEM_BYTES>>>(coord, cell,
                                             W0, b0, W1, b1, W2, b2, W3, b3,
                                             out);
}

// round 7
// speedup vs baseline: 4.4479x; 1.7859x over previous
#include <cuda_runtime.h>
#include <cuda_bf16.h>
#include <cstdint>

// ---------------------------------------------------------------------------
// LIIF3D fused kernel — mma.sync m16n8k16 bf16, split-precision hi+lo (R6).
// R5 (tf32 single-pass) was structurally correct, rel_err 1.016e-3 = pure
// tf32 rounding. This round: every value v = hi(bf16) + lo(bf16); each GEMM
// computes a_hi*b_hi + a_hi*b_lo + a_lo*b_hi (lo*lo dropped, ~2^-18).
// Error ~1e-5; cost 1.5x single tf32 at 2x the per-element rate.
//
// Per CTA: M=64 rows (8 queries x 8 shifts), N=256. 8 warps, warp-tile 64x32.
// Fragment-packed operand images -> all smem traffic is conflict-free LDS.128.
// cp.async 4-slot x 16KB ring, depth 3. Bias0 folded as const-1 column (K0=72,
// padded to 80). Epilogues rewrite A images in place; layer-2 fused into dot.
// ---------------------------------------------------------------------------

#define NQ        131072
#define QPB       8
#define GRID      (NQ / QPB)      // 16384 CTAs
#define THREADS   256
#define NSTEP_TOT 37              // k16 steps: 5 (L0,K=80) + 16 + 16

// smem offsets in u32 units
#define SU_AHI   0                 // A hi image: 8192 u32 (32KB)
#define SU_ALO   8192              // A lo image: 8192 u32
#define SU_RING  16384             // 4 chunks x 4096 u32 (64KB)
#define SU_AREA  32768             // 64
#define SU_PART  32832             // 512
#define SU_PRED  33344             // 64
#define SMEM_BYTES ((33344 + 64) * 4)   // 133632 B

// global scratch
__device__ float    g_feat_t[32 * 32 * 32 * 64]; // (z,y,x,c) channel-last, 8MB
__device__ unsigned g_w0s[5  * 4096];            // packed bf16 hi/lo weights
__device__ unsigned g_w1s[16 * 4096];
__device__ unsigned g_w2s[16 * 4096];

// ---------------- PTX helpers ----------------
__device__ __forceinline__ unsigned smem_u32p(const void* p) {
    unsigned r;
    asm("{ .reg .u64 t; cvta.to.shared.u64 t, %1; cvt.u32.u64 %0, t; }"
        : "=r"(r) : "l"(p));
    return r;
}
__device__ __forceinline__ void cp_async16(unsigned s, const void* g) {
    asm volatile("cp.async.ca.shared.global [%0], [%1], 16;" :: "r"(s), "l"(g));
}
__device__ __forceinline__ void cp_commit() { asm volatile("cp.async.commit_group;"); }
template <int N>
__device__ __forceinline__ void cp_waitg() {
    asm volatile("cp.async.wait_group %0;" :: "n"(N));
}
__device__ __forceinline__ void ring_wait(int rem) {
    if      (rem >= 2) cp_waitg<2>();
    else if (rem == 1) cp_waitg<1>();
    else               cp_waitg<0>();
}
// m16n8k16 bf16 mma, row.col, fp32 accumulate
__device__ __forceinline__ void mma16(float4& c, const uint4 a,
                                      const unsigned b0, const unsigned b1) {
    asm volatile(
        "mma.sync.aligned.m16n8k16.row.col.f32.bf16.bf16.f32 "
        "{%0,%1,%2,%3}, {%4,%5,%6,%7}, {%8,%9}, {%0,%1,%2,%3};"
        : "+f"(c.x), "+f"(c.y), "+f"(c.z), "+f"(c.w)
        : "r"(a.x), "r"(a.y), "r"(a.z), "r"(a.w), "r"(b0), "r"(b1));
}
// split (v0,v1) into bf16x2 hi word + bf16x2 lo word
__device__ __forceinline__ void split2(float v0, float v1,
                                       unsigned& hi, unsigned& lo) {
    __nv_bfloat162 h = __floats2bfloat162_rn(v0, v1);
    float h0 = __bfloat162float(h.x), h1 = __bfloat162float(h.y);
    __nv_bfloat162 l = __floats2bfloat162_rn(v0 - h0, v1 - h1);
    hi = *(unsigned*)&h;
    lo = *(unsigned*)&l;
}

// A-image u32 word index for (row, k-pair p) [p = k>>1]
// frag group (step,i,lane) holds 4 words: q = rlow + 2*phigh
__device__ __forceinline__ int xw(int row, int p) {
    const int step = p >> 3, pin = p & 7;
    const int i = row >> 4, g = row & 7, rl = (row >> 3) & 1;
    const int t4 = pin & 3, ph = pin >> 2;
    return (((step * 4 + i) * 32) + g * 4 + t4) * 4 + rl + 2 * ph;
}

// ---------------- prep: feat transpose ----------------
__global__ void transpose_feat(const float* __restrict__ feat) {
    __shared__ float tile[64][65];
    const int sp0 = blockIdx.x * 64;
    const int tx = threadIdx.x, ty = threadIdx.y;
    #pragma unroll
    for (int c = ty; c < 64; c += 4) tile[c][tx] = feat[c * 32768 + sp0 + tx];
    __syncthreads();
    #pragma unroll
    for (int s = ty; s < 64; s += 4)
        g_feat_t[(size_t)(sp0 + s) * 64 + tx] = tile[tx][s];
}

// ---------------- prep: packed bf16 hi/lo weight images ----------------
// chunk kb (K rows 16kb..16kb+15), u32 idx in chunk = ((w*4+s)*32 + lane)*4 + q
// s: 0=hi j01, 1=hi j23, 2=lo j01, 3=lo j23;  q: j_low = q>>1, breg = q&1
// word = bf16x2 of W[k0][n], W[k0+1][n], k0 = 16kb + 2t4 + 8*breg, n = 32w+8j+g
__global__ void prep_w(const float* __restrict__ W, const float* __restrict__ b,
                       int Kreal, int Kbias, unsigned* __restrict__ dst) {
    const int idx = blockIdx.x * 256 + threadIdx.x;
    const int kb = idx >> 12;
    const int f  = idx & 4095;
    const int q = f & 3;
    const int lane = (f >> 2) & 31;
    const int s = (f >> 7) & 3;
    const int w = f >> 9;
    const int g = lane >> 2, t4 = lane & 3;
    const int j = 2 * (s & 1) + (q >> 1);
    const int hl = s >> 1;
    const int n = 32 * w + 8 * j + g;
    const int k0 = 16 * kb + 2 * t4 + 8 * (q & 1);
    auto gv = [&](int k) -> float {
        if (k < Kreal)  return W[k * 256 + n];
        if (k == Kbias) return b[n];
        return 0.f;
    };
    unsigned hi, lo;
    split2(gv(k0), gv(k0 + 1), hi, lo);
    dst[idx] = hl ? lo : hi;
}

// ---------------- weight chunk source ----------------
__device__ __forceinline__ const unsigned* wsrc(int kk) {
    return kk < 5  ? g_w0s + kk * 4096
         : kk < 21 ? g_w1s + (kk - 5) * 4096
                   : g_w2s + (kk - 21) * 4096;
}
__device__ __forceinline__ void cp_chunk(unsigned dstb,
                                         const unsigned* __restrict__ src, int t) {
    const float4* s4 = (const float4*)src;
    #pragma unroll
    for (int i = 0; i < 4; i++)
        cp_async16(dstb + (unsigned)t * 64u + i * 16u, s4 + t * 4 + i);
    cp_commit();
}

// ---------------- main fused kernel ----------------
__global__ void __launch_bounds__(THREADS, 1)
liif_mma(const float* __restrict__ coord, const float* __restrict__ cell,
         const float* __restrict__ b1, const float* __restrict__ b2,
         const float* __restrict__ W3, const float* __restrict__ b3,
         float* __restrict__ out)
{
    extern __shared__ float sm[];
    unsigned* smu = (unsigned*)sm;
    unsigned* AH = smu + SU_AHI;
    unsigned* AL = smu + SU_ALO;
    const unsigned smb = smem_u32p(sm);
    const int t = threadIdx.x, w = t >> 5, lane = t & 31;
    const int g = lane >> 2, t4 = lane & 3;
    const int q0 = blockIdx.x * QPB;

    // prologue: prefetch first 3 weight chunks (overlaps sampling)
    #pragma unroll
    for (int c = 0; c < 3; c++)
        cp_chunk(smb + (SU_RING + c * 4096) * 4, wsrc(c), t);

    // ---- Stage A: trilinear sampling -> split X images (K=80 padded) ----
    #pragma unroll 1
    for (int it = 0; it < 8; it++) {
        const int rr = w + 8 * it;                 // 0..63
        const int q = q0 + (rr >> 3);
        const int s = rr & 7;
        const float c0 = coord[q * 3 + 0], c1 = coord[q * 3 + 1], c2 = coord[q * 3 + 2];
        const float l0 = cell[q * 3 + 0],  l1 = cell[q * 3 + 1],  l2 = cell[q * 3 + 2];
        const float r = 1.0f / 32.0f;
        float g0 = c0 + ((s & 4) ? r : -r) + 1e-6f;
        float g1 = c1 + ((s & 2) ? r : -r) + 1e-6f;
        float g2 = c2 + ((s & 1) ? r : -r) + 1e-6f;
        const float lo_ = -1.0f + 1e-6f, hi_ = 1.0f - 1e-6f;
        g0 = fminf(fmaxf(g0, lo_), hi_);
        g1 = fminf(fmaxf(g1, lo_), hi_);
        g2 = fminf(fmaxf(g2, lo_), hi_);
        const float z = (g0 + 1.0f) * 16.0f - 0.5f;
        const float y = (g1 + 1.0f) * 16.0f - 0.5f;
        const float x = (g2 + 1.0f) * 16.0f - 0.5f;
        const float zf = floorf(z), yf = floorf(y), xf = floorf(x);
        const float wz = z - zf, wy = y - yf, wx = x - xf;
        const int iz0 = min(max((int)zf, 0), 31), iz1 = min(max((int)zf + 1, 0), 31);
        const int iy0 = min(max((int)yf, 0), 31), iy1 = min(max((int)yf + 1, 0), 31);
        const int ix0 = min(max((int)xf, 0), 31), ix1 = min(max((int)xf + 1, 0), 31);
        const float st = 2.0f / 31.0f;
        const float qc0 = (1.0f - wx) * (-1.0f + ix0 * st) + wx * (-1.0f + ix1 * st);
        const float qc1 = (1.0f - wy) * (-1.0f + iy0 * st) + wy * (-1.0f + iy1 * st);
        const float qc2 = (1.0f - wz) * (-1.0f + iz0 * st) + wz * (-1.0f + iz1 * st);
        const float rc0 = (c0 - qc0) * 32.0f;
        const float rc1 = (c1 - qc1) * 32.0f;
        const float rc2 = (c2 - qc2) * 32.0f;

        const float w00 = (1.0f - wz) * (1.0f - wy), w01 = (1.0f - wz) * wy;
        const float w10 = wz * (1.0f - wy),          w11 = wz * wy;
        const float mwx = 1.0f - wx;
        const int b00 = (iz0 * 32 + iy0) * 32, b01 = (iz0 * 32 + iy1) * 32;
        const int b10 = (iz1 * 32 + iy0) * 32, b11 = (iz1 * 32 + iy1) * 32;
        const float* F = g_feat_t + lane * 2;      // lane owns channels 2l, 2l+1
        float2 acc = make_float2(0.f, 0.f);
        float2 v;
        v = *(const float2*)(F + (size_t)(b00 + ix0) * 64); acc.x += w00 * mwx * v.x; acc.y += w00 * mwx * v.y;
        v = *(const float2*)(F + (size_t)(b00 + ix1) * 64); acc.x += w00 * wx  * v.x; acc.y += w00 * wx  * v.y;
        v = *(const float2*)(F + (size_t)(b01 + ix0) * 64); acc.x += w01 * mwx * v.x; acc.y += w01 * mwx * v.y;
        v = *(const float2*)(F + (size_t)(b01 + ix1) * 64); acc.x += w01 * wx  * v.x; acc.y += w01 * wx  * v.y;
        v = *(const float2*)(F + (size_t)(b10 + ix0) * 64); acc.x += w10 * mwx * v.x; acc.y += w10 * mwx * v.y;
        v = *(const float2*)(F + (size_t)(b10 + ix1) * 64); acc.x += w10 * wx  * v.x; acc.y += w10 * wx  * v.y;
        v = *(const float2*)(F + (size_t)(b11 + ix0) * 64); acc.x += w11 * mwx * v.x; acc.y += w11 * mwx * v.y;
        v = *(const float2*)(F + (size_t)(b11 + ix1) * 64); acc.x += w11 * wx  * v.x; acc.y += w11 * wx  * v.y;

        unsigned hw, lw;
        split2(acc.x, acc.y, hw, lw);
        AH[xw(rr, lane)] = hw;                     // k-pair p = lane (k=2l,2l+1)
        AL[xw(rr, lane)] = lw;
        if (lane < 8) {                            // k-pairs 32..39 (k 64..79)
            float e0 = 0.f, e1 = 0.f;
            if (lane == 0) { e0 = rc0; e1 = rc1; }
            else if (lane == 1) { e0 = rc2; e1 = l0 * 32.0f; }
            else if (lane == 2) { e0 = l1 * 32.0f; e1 = l2 * 32.0f; }
            else if (lane == 3) {
                float cv = fabsf(l0 * l1 * l2);
                e0 = fminf(fmaxf(8.0f / (cv + 1e-8f), 1.0f), 64.0f);
                e1 = 1.0f;                         // folded bias b0
            }
            split2(e0, e1, hw, lw);
            AH[xw(rr, 32 + lane)] = hw;
            AL[xw(rr, 32 + lane)] = lw;
        }
        if (lane == 0) sm[SU_AREA + rr] = fabsf(rc0 * rc1 * rc2) + 1e-9f;
    }
    // (first step's __syncthreads orders X writes before A reads)

    float4 c[4][4];
    #pragma unroll
    for (int i = 0; i < 4; i++)
        #pragma unroll
        for (int j = 0; j < 4; j++) c[i][j] = make_float4(0.f, 0.f, 0.f, 0.f);

    const uint4* AH4 = (const uint4*)AH;
    const uint4* AL4 = (const uint4*)AL;
    const uint4* R4  = (const uint4*)(smu + SU_RING);

    int kk = 0;
    #pragma unroll 1
    for (int layer = 0; layer < 3; layer++) {
        const int nst = (layer == 0) ? 5 : 16;
        #pragma unroll 1
        for (int s = 0; s < nst; s++, kk++) {
            const int rem = NSTEP_TOT - 1 - kk;
            ring_wait(rem);
            __syncthreads();
            if (kk + 3 < NSTEP_TOT)   // slot (kk+3)&3 = (kk-1)&3, reads done
                cp_chunk(smb + (SU_RING + ((kk + 3) & 3) * 4096) * 4,
                         wsrc(kk + 3), t);

            const int sb = (kk & 3) * 1024;        // float4 units per chunk
            const uint4 bh0 = R4[sb + (w * 4 + 0) * 32 + lane];  // hi j0,j1
            const uint4 bh1 = R4[sb + (w * 4 + 1) * 32 + lane];  // hi j2,j3
            const uint4 bl0 = R4[sb + (w * 4 + 2) * 32 + lane];  // lo j0,j1
            const uint4 bl1 = R4[sb + (w * 4 + 3) * 32 + lane];  // lo j2,j3
            #pragma unroll
            for (int i = 0; i < 4; i++) {
                const uint4 ah = AH4[(s * 4 + i) * 32 + lane];
                const uint4 al = AL4[(s * 4 + i) * 32 + lane];
                mma16(c[i][0], ah, bh0.x, bh0.y);
                mma16(c[i][1], ah, bh0.z, bh0.w);
                mma16(c[i][2], ah, bh1.x, bh1.y);
                mma16(c[i][3], ah, bh1.z, bh1.w);
                mma16(c[i][0], ah, bl0.x, bl0.y);
                mma16(c[i][1], ah, bl0.z, bl0.w);
                mma16(c[i][2], ah, bl1.x, bl1.y);
                mma16(c[i][3], ah, bl1.z, bl1.w);
                mma16(c[i][0], al, bh0.x, bh0.y);
                mma16(c[i][1], al, bh0.z, bh0.w);
                mma16(c[i][2], al, bh1.x, bh1.y);
                mma16(c[i][3], al, bh1.z, bh1.w);
            }
        }
        __syncthreads();   // all warps done reading this layer's A images

        if (layer < 2) {
            // epilogue: relu(+bias) -> rewrite split A images in place
            const float* bias = (layer == 1) ? b1 : nullptr;
            #pragma unroll
            for (int j = 0; j < 4; j++) {
                const int col0 = 32 * w + 8 * j + 2 * t4;
                const int p = col0 >> 1;           // k-pair index
                const float ba = bias ? __ldg(bias + col0)     : 0.f;
                const float bb = bias ? __ldg(bias + col0 + 1) : 0.f;
                #pragma unroll
                for (int i = 0; i < 4; i++) {
                    const int r0 = 16 * i + g;
                    unsigned hw, lw;
                    split2(fmaxf(c[i][j].x + ba, 0.f), fmaxf(c[i][j].y + bb, 0.f), hw, lw);
                    AH[xw(r0, p)] = hw;  AL[xw(r0, p)] = lw;
                    split2(fmaxf(c[i][j].z + ba, 0.f), fmaxf(c[i][j].w + bb, 0.f), hw, lw);
                    AH[xw(r0 + 8, p)] = hw;  AL[xw(r0 + 8, p)] = lw;
                    c[i][j] = make_float4(0.f, 0.f, 0.f, 0.f);
                }
            }
        }
    }

    // ---- Final: p[m] = sum_k relu(D2[m,k]+b2[k]) * W3[k] ----
    {
        float pr[8];
        #pragma unroll
        for (int i = 0; i < 8; i++) pr[i] = 0.f;
        #pragma unroll
        for (int j = 0; j < 4; j++) {
            const int col0 = 32 * w + 8 * j + 2 * t4;
            const float ba = __ldg(b2 + col0),  bb = __ldg(b2 + col0 + 1);
            const float wa = __ldg(W3 + col0),  wb = __ldg(W3 + col0 + 1);
            #pragma unroll
            for (int i = 0; i < 4; i++) {
                pr[2 * i]     += fmaxf(c[i][j].x + ba, 0.f) * wa
                               + fmaxf(c[i][j].y + bb, 0.f) * wb;
                pr[2 * i + 1] += fmaxf(c[i][j].z + ba, 0.f) * wa
                               + fmaxf(c[i][j].w + bb, 0.f) * wb;
            }
        }
        #pragma unroll
        for (int i = 0; i < 8; i++) {
            pr[i] += __shfl_xor_sync(0xffffffffu, pr[i], 1);
            pr[i] += __shfl_xor_sync(0xffffffffu, pr[i], 2);
        }
        if (t4 == 0) {
            #pragma unroll
            for (int i = 0; i < 4; i++) {
                sm[SU_PART + (16 * i + g) * 8 + w]     = pr[2 * i];
                sm[SU_PART + (16 * i + g + 8) * 8 + w] = pr[2 * i + 1];
            }
        }
    }
    __syncthreads();
    if (t < 64) {
        float p = b3[0];
        #pragma unroll
        for (int w8 = 0; w8 < 8; w8++) p += sm[SU_PART + t * 8 + w8];
        sm[SU_PRED + t] = p;
    }
    __syncthreads();
    if (t < 8) {
        float tot = 0.f, o = 0.f;
        #pragma unroll
        for (int s = 0; s < 8; s++) tot += sm[SU_AREA + t * 8 + s];
        #pragma unroll
        for (int s = 0; s < 8; s++)
            o += sm[SU_PRED + t * 8 + s] * sm[SU_AREA + t * 8 + (7 - s)];
        out[q0 + t] = o / tot;
    }
}

// ---------------- launch ----------------
extern "C" void kernel_launch(void* const* d_in, const int* in_sizes, int n_in,
                              void* d_out, int out_size) {
    (void)in_sizes; (void)n_in; (void)out_size;
    const float* inp   = (const float*)d_in[0];
    const float* coord = (const float*)d_in[1];
    const float* cell  = (const float*)d_in[2];
    const float* W0 = (const float*)d_in[3];
    const float* b0 = (const float*)d_in[4];
    const float* W1 = (const float*)d_in[5];
    const float* b1 = (const float*)d_in[6];
    const float* W2 = (const float*)d_in[7];
    const float* b2 = (const float*)d_in[8];
    const float* W3 = (const float*)d_in[9];
    const float* b3 = (const float*)d_in[10];
    float* out = (float*)d_out;

    unsigned* w0s; cudaGetSymbolAddress((void**)&w0s, g_w0s);
    unsigned* w1s; cudaGetSymbolAddress((void**)&w1s, g_w1s);
    unsigned* w2s; cudaGetSymbolAddress((void**)&w2s, g_w2s);

    cudaFuncSetAttribute(liif_mma,
                         cudaFuncAttributeMaxDynamicSharedMemorySize, SMEM_BYTES);

    transpose_feat<<<512, dim3(64, 4)>>>(inp);
    prep_w<<<5 * 16, 256>>>(W0, b0, 71, 71, w0s);   // K=80, bias folded at 71
    prep_w<<<16 * 16, 256>>>(W1, b1, 256, -1, w1s);
    prep_w<<<16 * 16, 256>>>(W2, b2, 256, -1, w2s);
    liif_mma<<<GRID, THREADS, SMEM_BYTES>>>(coord, cell, b1, b2, W3, b3, out);
}